// round 17
// baseline (speedup 1.0000x reference)
#include <cuda_runtime.h>
#include <cstdint>

#define NN 50000
#define EE 800000
#define NBS 49   // ceil(NN/1024)

// ---------------- scratch (device globals; no allocation allowed) ----------------
__device__ __align__(16) float g_h0[(size_t)NN * 128];      // layer input features (fp32)
__device__ __align__(16) uint32_t g_h1[(size_t)NN * 64];    // h = x@W, f16x2 pairs (NN*128 halfs)
__device__ __align__(16) float g_asrc[NN * 4];
__device__ __align__(16) float g_adst[NN * 4];
__device__ int g_deg[NN];
__device__ int g_ptr[NN + 1];
__device__ int g_bsum[64];
__device__ int g_csr[EE + NN];
__device__ int g_is64;

// ---------------- tf32 / f16 helpers (inline PTX only; no cuda_fp16.h) ----------------
__device__ __forceinline__ uint32_t f2tf(float x) {
    uint32_t u;
    asm("cvt.rna.tf32.f32 %0, %1;" : "=r"(u) : "f"(x));
    return u;
}
__device__ __forceinline__ void mma_tf32(float* c, const uint32_t* a, uint32_t b0, uint32_t b1) {
    asm volatile(
        "mma.sync.aligned.m16n8k8.row.col.f32.tf32.tf32.f32 "
        "{%0,%1,%2,%3}, {%4,%5,%6,%7}, {%8,%9}, {%0,%1,%2,%3};"
        : "+f"(c[0]), "+f"(c[1]), "+f"(c[2]), "+f"(c[3])
        : "r"(a[0]), "r"(a[1]), "r"(a[2]), "r"(a[3]), "r"(b0), "r"(b1));
}
__device__ __forceinline__ uint32_t packh2(float lo, float hi) {
    uint32_t r;   // cvt.rn.f16x2.f32 d, a, b -> d.h1 = a, d.h0 = b
    asm("cvt.rn.f16x2.f32 %0, %1, %2;" : "=r"(r) : "f"(hi), "f"(lo));
    return r;
}
__device__ __forceinline__ float2 unpackh2(uint32_t u) {
    float lo, hi;
    asm("{\n\t.reg .b16 l, h;\n\tmov.b32 {l, h}, %2;\n\t"
        "cvt.f32.f16 %0, l;\n\tcvt.f32.f16 %1, h;\n\t}"
        : "=f"(lo), "=f"(hi) : "r"(u));
    return make_float2(lo, hi);
}
__device__ __forceinline__ float4 h4tof4(uint2 u) {
    float2 a = unpackh2(u.x), b = unpackh2(u.y);
    return make_float4(a.x, a.y, b.x, b.y);
}

// ---------------- CSR build ----------------
__global__ void detect_init_kernel(const int* __restrict__ e32) {
    int n = blockIdx.x * blockDim.x + threadIdx.x;
    if (n < NN) g_deg[n] = 1;   // self loop
    if (blockIdx.x == 0) {
        __shared__ int any;
        if (threadIdx.x == 0) any = 0;
        __syncthreads();
        int local = 0;
        for (int i = threadIdx.x; i < 4096; i += blockDim.x)
            if (e32[2 * i + 1] != 0) local = 1;
        if (local) any = 1;
        __syncthreads();
        if (threadIdx.x == 0) g_is64 = (any == 0) ? 1 : 0;
    }
}

__global__ void hist_kernel(const void* __restrict__ ei) {
    int e = blockIdx.x * blockDim.x + threadIdx.x;
    if (e >= EE) return;
    int d = g_is64 ? (int)((const long long*)ei)[EE + e]
                   : ((const int*)ei)[EE + e];
    atomicAdd(&g_deg[d], 1);
}

__global__ void scan_local_kernel() {
    __shared__ int wsum[32];
    int t = threadIdx.x;
    int i = blockIdx.x * 1024 + t;
    int v = (i < NN) ? g_deg[i] : 0;
    int x = v;
    #pragma unroll
    for (int off = 1; off < 32; off <<= 1) {
        int y = __shfl_up_sync(0xffffffffu, x, off);
        if ((t & 31) >= off) x += y;
    }
    if ((t & 31) == 31) wsum[t >> 5] = x;
    __syncthreads();
    if (t < 32) {
        int w = wsum[t];
        #pragma unroll
        for (int off = 1; off < 32; off <<= 1) {
            int y = __shfl_up_sync(0xffffffffu, w, off);
            if (t >= off) w += y;
        }
        wsum[t] = w;
    }
    __syncthreads();
    int incl = x + ((t >= 32) ? wsum[(t >> 5) - 1] : 0);
    if (i < NN) g_ptr[i] = incl - v;
    if (t == 1023) g_bsum[blockIdx.x] = incl;
}

__global__ void scan_add_kernel() {
    __shared__ int s_pref;
    int t = threadIdx.x;
    if (t < 32) {
        int carry = 0;
        for (int base = 0; base < NBS; base += 32) {
            int v = (base + t < NBS) ? g_bsum[base + t] : 0;
            int x = v;
            #pragma unroll
            for (int off = 1; off < 32; off <<= 1) {
                int y = __shfl_up_sync(0xffffffffu, x, off);
                if (t >= off) x += y;
            }
            if (base + t == (int)blockIdx.x) s_pref = carry + x - v;
            carry += __shfl_sync(0xffffffffu, x, 31);
        }
        if (blockIdx.x == 0 && t == 0) g_ptr[NN] = carry;
    }
    __syncthreads();
    int i = blockIdx.x * 1024 + t;
    if (i < NN) {
        int p = g_ptr[i] + s_pref;
        g_ptr[i] = p;
        g_csr[p] = i;    // self loop at slot 0
        g_deg[i] = 1;    // scatter cursor
    }
}

__global__ void scatter_kernel(const void* __restrict__ ei) {
    int e = blockIdx.x * blockDim.x + threadIdx.x;
    if (e >= EE) return;
    int s, d;
    if (g_is64) {
        s = (int)((const long long*)ei)[e];
        d = (int)((const long long*)ei)[EE + e];
    } else {
        s = ((const int*)ei)[e];
        d = ((const int*)ei)[EE + e];
    }
    int pos = atomicAdd(&g_deg[d], 1);
    g_csr[g_ptr[d] + pos] = s;
}

// ---------------- big GEMM via mma.sync tf32 (3xTF32), 512 threads, 2 blocks/SM ----------------
#define XP2 36   // xs pitch (floats) for 32-wide K chunk
#define WP 136   // ws pitch (floats)
#define SP 132   // stage pitch (floats)

__global__ __launch_bounds__(512, 2)
void gemm_tc_kernel(const float* __restrict__ X, const float* __restrict__ W,
                    const float* __restrict__ att_s, const float* __restrict__ att_d,
                    uint32_t* __restrict__ H, float* __restrict__ asrc,
                    float* __restrict__ adst) {
    extern __shared__ char sh[];
    float* att_ss = (float*)sh;                        // 128 f
    float* att_ds = (float*)(sh + 512);                // 128 f
    uint32_t* xs_hi = (uint32_t*)(sh + 1024);          // [128][XP2]
    uint32_t* xs_lo = xs_hi + 128 * XP2;
    uint32_t* ws_hi = xs_lo + 128 * XP2;               // [32][WP]
    uint32_t* ws_lo = ws_hi + 32 * WP;
    float* stage = (float*)(sh + 1024);                // reused after mma

    int t = threadIdx.x;
    int lane = t & 31, wid = t >> 5;
    int g = lane >> 2, tig = lane & 3;
    int wm = wid >> 2, wn = wid & 3;
    int n0 = blockIdx.x * 128;

    if (t < 128) { att_ss[t] = att_s[t]; att_ds[t] = att_d[t]; }

    float acc[2][4][4];
    #pragma unroll
    for (int mt = 0; mt < 2; ++mt)
        #pragma unroll
        for (int nt = 0; nt < 4; ++nt)
            #pragma unroll
            for (int i = 0; i < 4; ++i) acc[mt][nt][i] = 0.f;

    for (int kc = 0; kc < 4; ++kc) {
        #pragma unroll 2
        for (int idx = t; idx < 128 * 8; idx += 512) {
            int r = idx >> 3, c4 = idx & 7;
            int n = n0 + r;
            float4 v = make_float4(0.f, 0.f, 0.f, 0.f);
            if (n < NN) v = ((const float4*)X)[(size_t)n * 32 + kc * 8 + c4];
            float e[4] = {v.x, v.y, v.z, v.w};
            #pragma unroll
            for (int j = 0; j < 4; ++j) {
                uint32_t hu = f2tf(e[j]);
                float lo = e[j] - __uint_as_float(hu);
                xs_hi[r * XP2 + c4 * 4 + j] = hu;
                xs_lo[r * XP2 + c4 * 4 + j] = f2tf(lo);
            }
        }
        #pragma unroll 2
        for (int idx = t; idx < 32 * 32; idx += 512) {
            int kr = idx >> 5, c4 = idx & 31;
            float4 v = ((const float4*)W)[(size_t)(kc * 32 + kr) * 32 + c4];
            float e[4] = {v.x, v.y, v.z, v.w};
            #pragma unroll
            for (int j = 0; j < 4; ++j) {
                uint32_t hu = f2tf(e[j]);
                float lo = e[j] - __uint_as_float(hu);
                ws_hi[kr * WP + c4 * 4 + j] = hu;
                ws_lo[kr * WP + c4 * 4 + j] = f2tf(lo);
            }
        }
        __syncthreads();

        const uint32_t* xa_h = xs_hi + (wm * 32 + g) * XP2 + tig;
        const uint32_t* xa_l = xs_lo + (wm * 32 + g) * XP2 + tig;
        const uint32_t* wb_h = ws_hi + tig * WP + wn * 32 + g;
        const uint32_t* wb_l = ws_lo + tig * WP + wn * 32 + g;

        #pragma unroll
        for (int ks = 0; ks < 4; ++ks) {
            uint32_t ah[2][4], al[2][4];
            #pragma unroll
            for (int mt = 0; mt < 2; ++mt) {
                int base = mt * 16 * XP2 + ks * 8;
                ah[mt][0] = xa_h[base];
                ah[mt][1] = xa_h[base + 8 * XP2];
                ah[mt][2] = xa_h[base + 4];
                ah[mt][3] = xa_h[base + 8 * XP2 + 4];
                al[mt][0] = xa_l[base];
                al[mt][1] = xa_l[base + 8 * XP2];
                al[mt][2] = xa_l[base + 4];
                al[mt][3] = xa_l[base + 8 * XP2 + 4];
            }
            #pragma unroll
            for (int nt = 0; nt < 4; ++nt) {
                int boff = ks * 8 * WP + nt * 8;
                uint32_t bh0 = wb_h[boff], bh1 = wb_h[boff + 4 * WP];
                uint32_t bl0 = wb_l[boff], bl1 = wb_l[boff + 4 * WP];
                #pragma unroll
                for (int mt = 0; mt < 2; ++mt) {
                    mma_tf32(acc[mt][nt], ah[mt], bh0, bh1);   // hi*hi
                    mma_tf32(acc[mt][nt], al[mt], bh0, bh1);   // lo*hi
                    mma_tf32(acc[mt][nt], ah[mt], bl0, bl1);   // hi*lo
                }
            }
        }
        __syncthreads();
    }

    // ---- epilogue: attention dots (warp covers exactly head wn) ----
    #pragma unroll
    for (int mt = 0; mt < 2; ++mt) {
        #pragma unroll
        for (int rh = 0; rh < 2; ++rh) {
            int n = n0 + wm * 32 + mt * 16 + g + rh * 8;
            float ps = 0.f, pd = 0.f;
            #pragma unroll
            for (int nt = 0; nt < 4; ++nt) {
                #pragma unroll
                for (int ci = 0; ci < 2; ++ci) {
                    int col = wn * 32 + nt * 8 + 2 * tig + ci;
                    float a = acc[mt][nt][rh * 2 + ci];
                    ps += a * att_ss[col];
                    pd += a * att_ds[col];
                }
            }
            #pragma unroll
            for (int off = 1; off <= 2; off <<= 1) {
                ps += __shfl_xor_sync(0xffffffffu, ps, off);
                pd += __shfl_xor_sync(0xffffffffu, pd, off);
            }
            if (tig == 0 && n < NN) {
                asrc[n * 4 + wn] = ps;
                adst[n * 4 + wn] = pd;
            }
        }
    }

    // ---- stage accs to smem, then interleaved f16 H store [n][c][h] ----
    #pragma unroll
    for (int mt = 0; mt < 2; ++mt) {
        int rbase = wm * 32 + mt * 16 + g;
        #pragma unroll
        for (int nt = 0; nt < 4; ++nt) {
            int col = wn * 32 + nt * 8 + 2 * tig;
            stage[rbase * SP + col] = acc[mt][nt][0];
            stage[rbase * SP + col + 1] = acc[mt][nt][1];
            stage[(rbase + 8) * SP + col] = acc[mt][nt][2];
            stage[(rbase + 8) * SP + col + 1] = acc[mt][nt][3];
        }
    }
    __syncthreads();
    #pragma unroll 2
    for (int idx = t; idx < 128 * 32; idx += 512) {
        int r = idx >> 5, fc = idx & 31;
        int n = n0 + r;
        if (n < NN) {
            const float* sr = stage + r * SP;
            uint2 u;
            u.x = packh2(sr[fc], sr[32 + fc]);        // heads 0,1
            u.y = packh2(sr[64 + fc], sr[96 + fc]);   // heads 2,3
            ((uint2*)H)[(size_t)n * 32 + fc] = u;
        }
    }
}

// ---------------- layer-4 GEMM via mma.sync tf32 (3xTF32): 256 rows x 32 cols ----------------
#define WP32 40   // B pitch (floats)
#define SP32 36   // stage pitch (floats)

__global__ __launch_bounds__(256, 2)
void gemm32_tc_kernel(const float* __restrict__ X, const float* __restrict__ W,
                      const float* __restrict__ att_s, const float* __restrict__ att_d,
                      uint32_t* __restrict__ H, float* __restrict__ asrc,
                      float* __restrict__ adst) {
    extern __shared__ char sh[];
    float* att_ss = (float*)sh;                        // 32 f
    float* att_ds = (float*)(sh + 512);                // 32 f
    uint32_t* xs_hi = (uint32_t*)(sh + 1024);          // [256][XP2]
    uint32_t* xs_lo = xs_hi + 256 * XP2;
    uint32_t* ws_hi = xs_lo + 256 * XP2;               // [32][WP32]
    uint32_t* ws_lo = ws_hi + 32 * WP32;
    float* stage = (float*)(sh + 1024);                // reused after mma

    int t = threadIdx.x;
    int lane = t & 31, wid = t >> 5;
    int g = lane >> 2, tig = lane & 3;
    int wm = wid;
    int n0 = blockIdx.x * 256;

    if (t < 32) { att_ss[t] = att_s[t]; att_ds[t] = att_d[t]; }

    float acc[2][4][4];
    #pragma unroll
    for (int mt = 0; mt < 2; ++mt)
        #pragma unroll
        for (int nt = 0; nt < 4; ++nt)
            #pragma unroll
            for (int i = 0; i < 4; ++i) acc[mt][nt][i] = 0.f;

    for (int kc = 0; kc < 4; ++kc) {
        #pragma unroll 4
        for (int idx = t; idx < 256 * 8; idx += 256) {
            int r = idx >> 3, c4 = idx & 7;
            int n = n0 + r;
            float4 v = make_float4(0.f, 0.f, 0.f, 0.f);
            if (n < NN) v = ((const float4*)X)[(size_t)n * 32 + kc * 8 + c4];
            float e[4] = {v.x, v.y, v.z, v.w};
            #pragma unroll
            for (int j = 0; j < 4; ++j) {
                uint32_t hu = f2tf(e[j]);
                float lo = e[j] - __uint_as_float(hu);
                xs_hi[r * XP2 + c4 * 4 + j] = hu;
                xs_lo[r * XP2 + c4 * 4 + j] = f2tf(lo);
            }
        }
        if (t < 256) {
            int kr = t >> 3, c4 = t & 7;
            if (kr < 32) {
                float4 v = ((const float4*)W)[(size_t)(kc * 32 + kr) * 8 + c4];
                float e[4] = {v.x, v.y, v.z, v.w};
                #pragma unroll
                for (int j = 0; j < 4; ++j) {
                    uint32_t hu = f2tf(e[j]);
                    float lo = e[j] - __uint_as_float(hu);
                    ws_hi[kr * WP32 + c4 * 4 + j] = hu;
                    ws_lo[kr * WP32 + c4 * 4 + j] = f2tf(lo);
                }
            }
        }
        __syncthreads();

        const uint32_t* xa_h = xs_hi + (wm * 32 + g) * XP2 + tig;
        const uint32_t* xa_l = xs_lo + (wm * 32 + g) * XP2 + tig;
        const uint32_t* wb_h = ws_hi + tig * WP32 + g;
        const uint32_t* wb_l = ws_lo + tig * WP32 + g;

        #pragma unroll
        for (int ks = 0; ks < 4; ++ks) {
            uint32_t ah[2][4], al[2][4];
            #pragma unroll
            for (int mt = 0; mt < 2; ++mt) {
                int base = mt * 16 * XP2 + ks * 8;
                ah[mt][0] = xa_h[base];
                ah[mt][1] = xa_h[base + 8 * XP2];
                ah[mt][2] = xa_h[base + 4];
                ah[mt][3] = xa_h[base + 8 * XP2 + 4];
                al[mt][0] = xa_l[base];
                al[mt][1] = xa_l[base + 8 * XP2];
                al[mt][2] = xa_l[base + 4];
                al[mt][3] = xa_l[base + 8 * XP2 + 4];
            }
            #pragma unroll
            for (int nt = 0; nt < 4; ++nt) {
                int boff = ks * 8 * WP32 + nt * 8;
                uint32_t bh0 = wb_h[boff], bh1 = wb_h[boff + 4 * WP32];
                uint32_t bl0 = wb_l[boff], bl1 = wb_l[boff + 4 * WP32];
                #pragma unroll
                for (int mt = 0; mt < 2; ++mt) {
                    mma_tf32(acc[mt][nt], ah[mt], bh0, bh1);
                    mma_tf32(acc[mt][nt], al[mt], bh0, bh1);
                    mma_tf32(acc[mt][nt], ah[mt], bl0, bl1);
                }
            }
        }
        __syncthreads();
    }

    #pragma unroll
    for (int mt = 0; mt < 2; ++mt) {
        #pragma unroll
        for (int rh = 0; rh < 2; ++rh) {
            int n = n0 + wm * 32 + mt * 16 + g + rh * 8;
            float ps = 0.f, pd = 0.f;
            #pragma unroll
            for (int nt = 0; nt < 4; ++nt) {
                #pragma unroll
                for (int ci = 0; ci < 2; ++ci) {
                    int col = nt * 8 + 2 * tig + ci;
                    float a = acc[mt][nt][rh * 2 + ci];
                    ps += a * att_ss[col];
                    pd += a * att_ds[col];
                }
            }
            #pragma unroll
            for (int off = 1; off <= 2; off <<= 1) {
                ps += __shfl_xor_sync(0xffffffffu, ps, off);
                pd += __shfl_xor_sync(0xffffffffu, pd, off);
            }
            if (tig == 0 && n < NN) {
                asrc[n] = ps;
                adst[n] = pd;
            }
        }
    }

    #pragma unroll
    for (int mt = 0; mt < 2; ++mt) {
        int rbase = wm * 32 + mt * 16 + g;
        #pragma unroll
        for (int nt = 0; nt < 4; ++nt) {
            int col = nt * 8 + 2 * tig;
            stage[rbase * SP32 + col] = acc[mt][nt][0];
            stage[rbase * SP32 + col + 1] = acc[mt][nt][1];
            stage[(rbase + 8) * SP32 + col] = acc[mt][nt][2];
            stage[(rbase + 8) * SP32 + col + 1] = acc[mt][nt][3];
        }
    }
    __syncthreads();
    #pragma unroll 4
    for (int idx = t; idx < 256 * 8; idx += 256) {
        int r = idx >> 3, fc = idx & 7;
        int n = n0 + r;
        if (n < NN) {
            const float* sr = stage + r * SP32 + fc * 4;
            uint2 u;
            u.x = packh2(sr[0], sr[1]);
            u.y = packh2(sr[2], sr[3]);
            ((uint2*)H)[(size_t)n * 8 + fc] = u;   // plain [n][32] half layout
        }
    }
}

// ---------------- per-node ONLINE softmax + aggregation (f16 feature gather) ----------------
__device__ __forceinline__ float lrelu(float v) { return fmaxf(v, 0.2f * v); }

template <int HEADS, int ACT>   // ACT: 0 = ELU, 1 = sigmoid
__launch_bounds__(256)
__global__ void agg_kernel(const uint32_t* __restrict__ feat,
                           const float* __restrict__ asrc, const float* __restrict__ adst,
                           const float* __restrict__ bias, float* __restrict__ out) {
    __shared__ float4 s_w4[8][32];
    __shared__ int s_src[8][32];
    int wid = threadIdx.x >> 5;
    int lane = threadIdx.x & 31;
    int n = blockIdx.x * 8 + wid;
    if (n >= NN) return;
    int beg = g_ptr[n], end = g_ptr[n + 1];
    const uint2* feat2 = (const uint2*)feat;   // 4 halfs per (node, channel)

    if (HEADS == 4) {
        float4 ad = ((const float4*)adst)[n];
        float m0 = -1e30f, m1 = -1e30f, m2 = -1e30f, m3 = -1e30f;
        float a0 = 0.f, a1 = 0.f, a2 = 0.f, a3 = 0.f;
        float s0 = 0.f, s1 = 0.f, s2 = 0.f, s3 = 0.f;
        for (int base = beg; base < end; base += 32) {
            int cnt = min(32, end - base);
            float l0 = -1e30f, l1 = -1e30f, l2 = -1e30f, l3 = -1e30f;
            int src = 0;
            if (lane < cnt) {
                src = g_csr[base + lane];
                float4 a = ((const float4*)asrc)[src];
                l0 = lrelu(a.x + ad.x);
                l1 = lrelu(a.y + ad.y);
                l2 = lrelu(a.z + ad.z);
                l3 = lrelu(a.w + ad.w);
            }
            float c0 = l0, c1 = l1, c2 = l2, c3 = l3;
            #pragma unroll
            for (int off = 16; off >= 1; off >>= 1) {
                c0 = fmaxf(c0, __shfl_xor_sync(0xffffffffu, c0, off));
                c1 = fmaxf(c1, __shfl_xor_sync(0xffffffffu, c1, off));
                c2 = fmaxf(c2, __shfl_xor_sync(0xffffffffu, c2, off));
                c3 = fmaxf(c3, __shfl_xor_sync(0xffffffffu, c3, off));
            }
            float nm0 = fmaxf(m0, c0), nm1 = fmaxf(m1, c1);
            float nm2 = fmaxf(m2, c2), nm3 = fmaxf(m3, c3);
            float f0 = __expf(m0 - nm0), f1 = __expf(m1 - nm1);
            float f2 = __expf(m2 - nm2), f3 = __expf(m3 - nm3);
            a0 *= f0; a1 *= f1; a2 *= f2; a3 *= f3;
            s0 *= f0; s1 *= f1; s2 *= f2; s3 *= f3;
            m0 = nm0; m1 = nm1; m2 = nm2; m3 = nm3;
            if (lane < cnt) {
                float4 wv;
                wv.x = __expf(l0 - m0);
                wv.y = __expf(l1 - m1);
                wv.z = __expf(l2 - m2);
                wv.w = __expf(l3 - m3);
                s_w4[wid][lane] = wv;
                s_src[wid][lane] = src;
            }
            __syncwarp();
            int i = 0;
            for (; i + 4 <= cnt; i += 4) {   // MLP=4: 4 independent gathers in flight
                float4 w0 = s_w4[wid][i],     w1 = s_w4[wid][i + 1];
                float4 w2 = s_w4[wid][i + 2], w3 = s_w4[wid][i + 3];
                int p0 = s_src[wid][i],     p1 = s_src[wid][i + 1];
                int p2 = s_src[wid][i + 2], p3 = s_src[wid][i + 3];
                uint2 u0 = feat2[(size_t)p0 * 32 + lane];
                uint2 u1 = feat2[(size_t)p1 * 32 + lane];
                uint2 u2 = feat2[(size_t)p2 * 32 + lane];
                uint2 u3 = feat2[(size_t)p3 * 32 + lane];
                float4 v0 = h4tof4(u0), v1 = h4tof4(u1);
                float4 v2 = h4tof4(u2), v3 = h4tof4(u3);
                a0 += w0.x * v0.x; a1 += w0.y * v0.y; a2 += w0.z * v0.z; a3 += w0.w * v0.w;
                a0 += w1.x * v1.x; a1 += w1.y * v1.y; a2 += w1.z * v1.z; a3 += w1.w * v1.w;
                a0 += w2.x * v2.x; a1 += w2.y * v2.y; a2 += w2.z * v2.z; a3 += w2.w * v2.w;
                a0 += w3.x * v3.x; a1 += w3.y * v3.y; a2 += w3.z * v3.z; a3 += w3.w * v3.w;
                s0 += w0.x + w1.x + w2.x + w3.x;
                s1 += w0.y + w1.y + w2.y + w3.y;
                s2 += w0.z + w1.z + w2.z + w3.z;
                s3 += w0.w + w1.w + w2.w + w3.w;
            }
            for (; i < cnt; ++i) {
                float4 wv = s_w4[wid][i];
                int si = s_src[wid][i];
                float4 v = h4tof4(feat2[(size_t)si * 32 + lane]);
                a0 += wv.x * v.x; a1 += wv.y * v.y; a2 += wv.z * v.z; a3 += wv.w * v.w;
                s0 += wv.x; s1 += wv.y; s2 += wv.z; s3 += wv.w;
            }
            __syncwarp();
        }
        float o0 = a0 / s0 + bias[lane];
        float o1 = a1 / s1 + bias[32 + lane];
        float o2 = a2 / s2 + bias[64 + lane];
        float o3 = a3 / s3 + bias[96 + lane];
        o0 = (o0 > 0.f) ? o0 : (__expf(o0) - 1.f);
        o1 = (o1 > 0.f) ? o1 : (__expf(o1) - 1.f);
        o2 = (o2 > 0.f) ? o2 : (__expf(o2) - 1.f);
        o3 = (o3 > 0.f) ? o3 : (__expf(o3) - 1.f);
        size_t b = (size_t)n * 128;
        out[b + lane] = o0;
        out[b + 32 + lane] = o1;
        out[b + 64 + lane] = o2;
        out[b + 96 + lane] = o3;
    } else {
        float* s_wf = (float*)&s_w4[wid][0];
        float ad = adst[n];
        float m = -1e30f, acc = 0.f, ssum = 0.f;
        int word = lane >> 1, half = lane & 1;
        for (int base = beg; base < end; base += 32) {
            int cnt = min(32, end - base);
            float l = -1e30f;
            int src = 0;
            if (lane < cnt) {
                src = g_csr[base + lane];
                l = lrelu(asrc[src] + ad);
            }
            float c = l;
            #pragma unroll
            for (int off = 16; off >= 1; off >>= 1)
                c = fmaxf(c, __shfl_xor_sync(0xffffffffu, c, off));
            float nm = fmaxf(m, c);
            float f = __expf(m - nm);
            acc *= f; ssum *= f;
            m = nm;
            if (lane < cnt) {
                s_wf[lane] = __expf(l - m);
                s_src[wid][lane] = src;
            }
            __syncwarp();
            int i = 0;
            for (; i + 4 <= cnt; i += 4) {
                float w0 = s_wf[i], w1 = s_wf[i + 1], w2 = s_wf[i + 2], w3 = s_wf[i + 3];
                int p0 = s_src[wid][i],     p1 = s_src[wid][i + 1];
                int p2 = s_src[wid][i + 2], p3 = s_src[wid][i + 3];
                float2 f0 = unpackh2(feat[(size_t)p0 * 16 + word]);
                float2 f1 = unpackh2(feat[(size_t)p1 * 16 + word]);
                float2 f2v = unpackh2(feat[(size_t)p2 * 16 + word]);
                float2 f3v = unpackh2(feat[(size_t)p3 * 16 + word]);
                float v0 = half ? f0.y : f0.x;
                float v1 = half ? f1.y : f1.x;
                float v2 = half ? f2v.y : f2v.x;
                float v3 = half ? f3v.y : f3v.x;
                acc += w0 * v0 + w1 * v1 + w2 * v2 + w3 * v3;
                ssum += w0 + w1 + w2 + w3;
            }
            for (; i < cnt; ++i) {
                float wi = s_wf[i];
                int si = s_src[wid][i];
                float2 fv = unpackh2(feat[(size_t)si * 16 + word]);
                acc += wi * (half ? fv.y : fv.x);
                ssum += wi;
            }
            __syncwarp();
        }
        float o = acc / ssum + bias[lane];
        o = 1.f / (1.f + __expf(-o));
        out[(size_t)n * 32 + lane] = o;
    }
}

// ---------------- host launcher (single stream, capture-safe) ----------------
extern "C" void kernel_launch(void* const* d_in, const int* in_sizes, int n_in,
                              void* d_out, int out_size) {
    const float* x = (const float*)d_in[0];
    const void* ei = d_in[1];
    const float* W[4]  = {(const float*)d_in[2], (const float*)d_in[6],
                          (const float*)d_in[10], (const float*)d_in[14]};
    const float* As[4] = {(const float*)d_in[3], (const float*)d_in[7],
                          (const float*)d_in[11], (const float*)d_in[15]};
    const float* Ad[4] = {(const float*)d_in[4], (const float*)d_in[8],
                          (const float*)d_in[12], (const float*)d_in[16]};
    const float* B[4]  = {(const float*)d_in[5], (const float*)d_in[9],
                          (const float*)d_in[13], (const float*)d_in[17]};
    float* out = (float*)d_out;

    float *p_h0, *p_asrc, *p_adst;
    uint32_t* p_h1;
    cudaGetSymbolAddress((void**)&p_h0, g_h0);
    cudaGetSymbolAddress((void**)&p_h1, g_h1);
    cudaGetSymbolAddress((void**)&p_asrc, g_asrc);
    cudaGetSymbolAddress((void**)&p_adst, g_adst);

    constexpr int SMEM_TC = 1024 + (2 * 128 * XP2 + 2 * 32 * WP) * 4;    // 72704 B
    constexpr int SMEM_32 = 1024 + (2 * 256 * XP2 + 2 * 32 * WP32) * 4;  // 84992 B
    cudaFuncSetAttribute(gemm_tc_kernel,
                         cudaFuncAttributeMaxDynamicSharedMemorySize, SMEM_TC);
    cudaFuncSetAttribute(gemm32_tc_kernel,
                         cudaFuncAttributeMaxDynamicSharedMemorySize, SMEM_32);

    const int GTC = (NN + 127) / 128;   // 391
    const int G32 = (NN + 255) / 256;   // 196
    const int AB = (NN + 7) / 8;        // 6250

    // CSR build (fused launches); layer-1 GEMM at index 3 for ncu capture.
    detect_init_kernel<<<(NN + 255) / 256, 256>>>((const int*)ei);         // 0
    hist_kernel<<<(EE + 255) / 256, 256>>>(ei);                            // 1
    scan_local_kernel<<<NBS, 1024>>>();                                    // 2
    gemm_tc_kernel<<<GTC, 512, SMEM_TC>>>(x, W[0], As[0], Ad[0],           // 3 (profiled)
                                          p_h1, p_asrc, p_adst);
    scan_add_kernel<<<NBS, 1024>>>();                                      // 4
    scatter_kernel<<<(EE + 255) / 256, 256>>>(ei);                         // 5

    // layer 1 aggregation
    agg_kernel<4, 0><<<AB, 256>>>(p_h1, p_asrc, p_adst, B[0], p_h0);
    // layer 2
    gemm_tc_kernel<<<GTC, 512, SMEM_TC>>>(p_h0, W[1], As[1], Ad[1], p_h1, p_asrc, p_adst);
    agg_kernel<4, 0><<<AB, 256>>>(p_h1, p_asrc, p_adst, B[1], p_h0);
    // layer 3
    gemm_tc_kernel<<<GTC, 512, SMEM_TC>>>(p_h0, W[2], As[2], Ad[2], p_h1, p_asrc, p_adst);
    agg_kernel<4, 0><<<AB, 256>>>(p_h1, p_asrc, p_adst, B[2], p_h0);
    // layer 4 (heads=1, 32 labels) -> sigmoid -> d_out
    gemm32_tc_kernel<<<G32, 256, SMEM_32>>>(p_h0, W[3], As[3], Ad[3], p_h1, p_asrc, p_adst);
    agg_kernel<1, 1><<<AB, 256>>>(p_h1, p_asrc, p_adst, B[3], out);
}